// round 6
// baseline (speedup 1.0000x reference)
#include <cuda_runtime.h>
#include <cuda_bf16.h>
#include <math.h>
#include <stdint.h>

// ---------------------------------------------------------------------------
// BSPLoss: out = lam1 + 0.5*(lam2+lam3), lam_i = top eigenvalue of F_i^T F_i.
// Gram (4-way K-split, proven R5 kernel) + 8 Frobenius-normalized symmetric
// squarings (new 8-warp in-CTA-K-split kernel) + 18-step power iteration on
// H_8 (weight 2^-8) replacing the last two squarings.
// All GEMMs: mma.sync.m16n8k16 bf16 hi/lo split (3 products, fp32 accum),
// upper-triangle tiles, mirrored store, fused Frobenius.
// ---------------------------------------------------------------------------

#define DIM    1024
#define NROWS  8192
#define M_SQ   8
#define NTILE  36
#define KSPLIT 4
#define PWR_M  18
#define PWR_CTAS 32

// Gram kernel (KC=16, 128 threads)
#define KCG     16
#define GREGB   4096
#define GSTAGEB (4 * GREGB)
#define GSMEMB  (2 * GSTAGEB + 1024)

// Squaring kernel (KC=32, 256 threads, in-CTA K-split)
#define KCS     32
#define SREGB   8192
#define SSTAGEB (4 * SREGB)
#define RED_STRIDE 130
#define SQ_SMEM 68608

__device__ __align__(16) float g_bufA[3][DIM * DIM];
__device__ __align__(16) float g_bufB[3][DIM * DIM];
__device__ __align__(16) float g_part[KSPLIT][3][DIM * DIM];
__device__ __align__(16) float g_vec[3][2][DIM];
__device__ double g_frob[3];
__device__ float  g_inv[3];
__device__ double g_logacc[3];
__device__ int    g_ctr[3];
__device__ float  g_pn[3][2];
__device__ int    g_bcnt;
__device__ int    g_bgen;

__global__ void init_kernel() {
    int i = threadIdx.x;
    if (i < 3) {
        g_frob[i] = 0.0; g_inv[i] = 1.0f; g_logacc[i] = 0.0; g_ctr[i] = 0;
        g_pn[i][0] = 0.0f; g_pn[i][1] = 0.0f;
    }
    if (i == 3) { g_bcnt = 0; g_bgen = 0; }
}

__device__ __forceinline__ uint32_t smem_u32(const void* p) {
    uint32_t a;
    asm("{ .reg .u64 t; cvta.to.shared.u64 t, %1; cvt.u32.u64 %0, t; }"
        : "=r"(a) : "l"(p));
    return a;
}

__device__ __forceinline__ void ldsm4t(uint32_t* r, uint32_t addr) {
    asm volatile("ldmatrix.sync.aligned.m8n8.x4.trans.shared.b16 {%0,%1,%2,%3}, [%4];"
                 : "=r"(r[0]), "=r"(r[1]), "=r"(r[2]), "=r"(r[3]) : "r"(addr));
}

__device__ __forceinline__ void mma16816(float* c, const uint32_t* a,
                                         uint32_t b0, uint32_t b1) {
    asm volatile("mma.sync.aligned.m16n8k16.row.col.f32.bf16.bf16.f32 "
                 "{%0,%1,%2,%3}, {%4,%5,%6,%7}, {%8,%9}, {%0,%1,%2,%3};"
                 : "+f"(c[0]), "+f"(c[1]), "+f"(c[2]), "+f"(c[3])
                 : "r"(a[0]), "r"(a[1]), "r"(a[2]), "r"(a[3]), "r"(b0), "r"(b1));
}

__device__ __forceinline__ uint32_t swz(uint32_t base, int row, int chunk) {
    return base + row * 256 + ((chunk ^ (row & 7)) << 4);
}

__device__ __forceinline__ void cvt_hl(float4 v, uint2& hi, uint2& lo) {
    __nv_bfloat162 h0 = __floats2bfloat162_rn(v.x, v.y);
    __nv_bfloat162 h1 = __floats2bfloat162_rn(v.z, v.w);
    __nv_bfloat162 l0 = __floats2bfloat162_rn(v.x - __bfloat162float(h0.x),
                                              v.y - __bfloat162float(h0.y));
    __nv_bfloat162 l1 = __floats2bfloat162_rn(v.z - __bfloat162float(h1.x),
                                              v.w - __bfloat162float(h1.y));
    hi.x = *(uint32_t*)&h0; hi.y = *(uint32_t*)&h1;
    lo.x = *(uint32_t*)&l0; lo.y = *(uint32_t*)&l1;
}

// Store one stage: row = k-row, c4 = column group. regb = operand region size.
__device__ __forceinline__ void store_stage(char* bufp, const float4* rI,
                                            const float4* rJ, int row, int c4,
                                            uint32_t regb) {
#pragma unroll
    for (int it = 0; it < 4; it++) {
        const int col4 = c4 + it * 8;
        const int chunk = col4 >> 1;
        const uint32_t off = (uint32_t)(row * 256) +
                             ((chunk ^ (row & 7)) << 4) + ((col4 & 1) * 8);
        uint2 hi, lo;
        cvt_hl(rI[it], hi, lo);
        *(uint2*)(bufp + off)        = hi;
        *(uint2*)(bufp + regb + off) = lo;
        cvt_hl(rJ[it], hi, lo);
        *(uint2*)(bufp + 2 * regb + off) = hi;
        *(uint2*)(bufp + 3 * regb + off) = lo;
    }
}

// One k16 step: 16 ldsm + 96 MMAs (warp tile 64x64).
__device__ __forceinline__ void compute_k16(uint32_t IHI, uint32_t ILO,
                                            uint32_t JHI, uint32_t JLO,
                                            float acc[4][8][4],
                                            int wm, int wn, int g, int tr,
                                            int krow0) {
    const int rowA = krow0 + ((g & 2) ? 8 : 0) + tr;
    const int rowB = krow0 + ((g & 1) ? 8 : 0) + tr;
    uint32_t ax[4][4], bh[4][4], bx[4][4];
#pragma unroll
    for (int mi = 0; mi < 4; mi++)
        ldsm4t(ax[mi], swz(IHI, rowA, (wm >> 3) + mi * 2 + (g & 1)));
#pragma unroll
    for (int nb = 0; nb < 4; nb++)
        ldsm4t(bh[nb], swz(JHI, rowB, (wn >> 3) + nb * 2 + (g >> 1)));
#pragma unroll
    for (int mi = 0; mi < 4; mi++)
#pragma unroll
        for (int nj = 0; nj < 8; nj++)
            mma16816(acc[mi][nj], ax[mi],
                     bh[nj >> 1][(nj & 1) * 2], bh[nj >> 1][(nj & 1) * 2 + 1]);
#pragma unroll
    for (int nb = 0; nb < 4; nb++)
        ldsm4t(bx[nb], swz(JLO, rowB, (wn >> 3) + nb * 2 + (g >> 1)));
#pragma unroll
    for (int mi = 0; mi < 4; mi++)
#pragma unroll
        for (int nj = 0; nj < 8; nj++)
            mma16816(acc[mi][nj], ax[mi],
                     bx[nj >> 1][(nj & 1) * 2], bx[nj >> 1][(nj & 1) * 2 + 1]);
#pragma unroll
    for (int mi = 0; mi < 4; mi++)
        ldsm4t(ax[mi], swz(ILO, rowA, (wm >> 3) + mi * 2 + (g & 1)));
#pragma unroll
    for (int mi = 0; mi < 4; mi++)
#pragma unroll
        for (int nj = 0; nj < 8; nj++)
            mma16816(acc[mi][nj], ax[mi],
                     bh[nj >> 1][(nj & 1) * 2], bh[nj >> 1][(nj & 1) * 2 + 1]);
}

// ============ Gram kernel (R5, proven): 128 thr, KC=16, K-split grid ========
__global__ void __launch_bounds__(128)
ata_mma_kernel(const float* __restrict__ a0, const float* __restrict__ a1,
               const float* __restrict__ a2, int Kper)
{
    extern __shared__ __align__(16) char dynsmem[];

    const int z = blockIdx.z;
    const float* A = (z == 0) ? a0 : ((z == 1) ? a1 : a2);
    float* C = g_part[blockIdx.y][z];

    int t = blockIdx.x, bi = 0;
    while (t >= 8 - bi) { t -= 8 - bi; bi++; }
    const int bj = bi + t;
    const int i0 = bi * 128, j0 = bj * 128;

    const int tid = threadIdx.x;
    const int w = tid >> 5, l = tid & 31;
    const int wm = (w >> 1) * 64, wn = (w & 1) * 64;
    const int tr = l & 7, g = l >> 3;
    const int row = tid >> 3, c4 = tid & 7;

    const uint32_t sb = smem_u32(dynsmem);
    const uint32_t ab = (sb + 1023u) & ~1023u;
    char* aptr = dynsmem + (ab - sb);

    float acc[4][8][4];
#pragma unroll
    for (int mi = 0; mi < 4; mi++)
#pragma unroll
        for (int nj = 0; nj < 8; nj++)
#pragma unroll
            for (int q = 0; q < 4; q++) acc[mi][nj][q] = 0.0f;

    const size_t kbase = (size_t)blockIdx.y * Kper;
    const float* pI = A + kbase * DIM + i0 + c4 * 4;
    const float* pJ = A + kbase * DIM + j0 + c4 * 4;

    const int S = Kper / KCG;
    float4 rI[4], rJ[4];

    {
        const size_t b0 = (size_t)row * DIM;
#pragma unroll
        for (int it = 0; it < 4; it++) {
            rI[it] = *(const float4*)(pI + b0 + it * 32);
            rJ[it] = *(const float4*)(pJ + b0 + it * 32);
        }
    }
    store_stage(aptr, rI, rJ, row, c4, GREGB);
    {
        const size_t b1 = (size_t)(KCG + row) * DIM;
#pragma unroll
        for (int it = 0; it < 4; it++) {
            rI[it] = *(const float4*)(pI + b1 + it * 32);
            rJ[it] = *(const float4*)(pJ + b1 + it * 32);
        }
    }
    __syncthreads();

    for (int s = 0; s < S; s++) {
        const int b = s & 1;
        if (s + 1 < S)
            store_stage(aptr + (b ^ 1) * GSTAGEB, rI, rJ, row, c4, GREGB);
        if (s + 2 < S) {
            const size_t bb = (size_t)((s + 2) * KCG + row) * DIM;
#pragma unroll
            for (int it = 0; it < 4; it++) {
                rI[it] = *(const float4*)(pI + bb + it * 32);
                rJ[it] = *(const float4*)(pJ + bb + it * 32);
            }
        }
        const uint32_t u = ab + b * GSTAGEB;
        compute_k16(u, u + GREGB, u + 2 * GREGB, u + 3 * GREGB,
                    acc, wm, wn, g, tr, 0);
        __syncthreads();
    }

    const int r  = l >> 2;
    const int c2 = 2 * (l & 3);
#pragma unroll
    for (int mi = 0; mi < 4; mi++) {
#pragma unroll
        for (int nj = 0; nj < 8; nj++) {
            float* a = acc[mi][nj];
            const int gr = i0 + wm + mi * 16 + r;
            const int gc = j0 + wn + nj * 8 + c2;
            *(float2*)&C[(size_t)gr * DIM + gc]       = make_float2(a[0], a[1]);
            *(float2*)&C[(size_t)(gr + 8) * DIM + gc] = make_float2(a[2], a[3]);
            if (bi != bj) {
                C[(size_t)gc * DIM + gr]           = a[0];
                C[(size_t)(gc + 1) * DIM + gr]     = a[1];
                C[(size_t)gc * DIM + gr + 8]       = a[2];
                C[(size_t)(gc + 1) * DIM + gr + 8] = a[3];
            }
        }
    }
}

// ============ Squaring kernel: 256 thr, 8 warps, KC=32 in-CTA K-split =======
__global__ void __launch_bounds__(256, 1)
sq_mma_kernel(int src_sel, int dst_sel, double wfin)
{
    extern __shared__ __align__(16) char dynsmem[];
    __shared__ float sh_wsum[4];

    const int z = blockIdx.z;
    const float* A = (src_sel == 1) ? g_bufA[z] : g_bufB[z];
    float* C       = (dst_sel == 1) ? g_bufA[z] : g_bufB[z];

    int t = blockIdx.x, bi = 0;
    while (t >= 8 - bi) { t -= 8 - bi; bi++; }
    const int bj = bi + t;
    const int i0 = bi * 128, j0 = bj * 128;

    const int tid = threadIdx.x;
    const int w = tid >> 5, l = tid & 31;
    const int ksub = w >> 2;            // 0 or 1: k-half of each stage
    const int q = w & 3;
    const int wm = (q >> 1) * 64, wn = (q & 1) * 64;
    const int tr = l & 7, g = l >> 3;
    const int row = tid >> 3, c4 = tid & 7;   // loader: rows 0..31

    const float sv = g_inv[z];
    const float s2 = sv * sv;

    const uint32_t sb = smem_u32(dynsmem);
    const uint32_t ab = (sb + 1023u) & ~1023u;
    char* aptr = dynsmem + (ab - sb);

    float acc[4][8][4];
#pragma unroll
    for (int mi = 0; mi < 4; mi++)
#pragma unroll
        for (int nj = 0; nj < 8; nj++)
#pragma unroll
            for (int qq = 0; qq < 4; qq++) acc[mi][nj][qq] = 0.0f;

    const float* pI = A + i0 + c4 * 4;
    const float* pJ = A + j0 + c4 * 4;

    const int S = DIM / KCS;  // 32 stages
    float4 rI[4], rJ[4];

    {
        const size_t b0 = (size_t)row * DIM;
#pragma unroll
        for (int it = 0; it < 4; it++) {
            rI[it] = *(const float4*)(pI + b0 + it * 32);
            rJ[it] = *(const float4*)(pJ + b0 + it * 32);
        }
    }
    store_stage(aptr, rI, rJ, row, c4, SREGB);
    {
        const size_t b1 = (size_t)(KCS + row) * DIM;
#pragma unroll
        for (int it = 0; it < 4; it++) {
            rI[it] = *(const float4*)(pI + b1 + it * 32);
            rJ[it] = *(const float4*)(pJ + b1 + it * 32);
        }
    }
    __syncthreads();

    for (int s = 0; s < S; s++) {
        const int b = s & 1;
        if (s + 1 < S)
            store_stage(aptr + (b ^ 1) * SSTAGEB, rI, rJ, row, c4, SREGB);
        if (s + 2 < S) {
            const size_t bb = (size_t)((s + 2) * KCS + row) * DIM;
#pragma unroll
            for (int it = 0; it < 4; it++) {
                rI[it] = *(const float4*)(pI + bb + it * 32);
                rJ[it] = *(const float4*)(pJ + bb + it * 32);
            }
        }
        const uint32_t u = ab + b * SSTAGEB;
        compute_k16(u, u + SREGB, u + 2 * SREGB, u + 3 * SREGB,
                    acc, wm, wn, g, tr, ksub * 16);
        __syncthreads();
    }

    // ---- merge the two k-halves through padded smem ----
    float* red = (float*)aptr;
    if (ksub == 1) {
#pragma unroll
        for (int mi = 0; mi < 4; mi++)
#pragma unroll
            for (int nj = 0; nj < 8; nj++) {
                const int rl = wm + mi * 16 + (l >> 2);
                const int cl = wn + nj * 8 + 2 * (l & 3);
                *(float2*)&red[rl * RED_STRIDE + cl] =
                    make_float2(acc[mi][nj][0], acc[mi][nj][1]);
                *(float2*)&red[(rl + 8) * RED_STRIDE + cl] =
                    make_float2(acc[mi][nj][2], acc[mi][nj][3]);
            }
    }
    __syncthreads();

    float fr = 0.0f;
    if (ksub == 0) {
        const float w2 = (bi == bj) ? 1.0f : 2.0f;
        const int r  = l >> 2;
        const int c2 = 2 * (l & 3);
#pragma unroll
        for (int mi = 0; mi < 4; mi++) {
#pragma unroll
            for (int nj = 0; nj < 8; nj++) {
                float* a = acc[mi][nj];
                const int rl = wm + mi * 16 + r;
                const int cl = wn + nj * 8 + c2;
                float2 v0 = *(float2*)&red[rl * RED_STRIDE + cl];
                float2 v1 = *(float2*)&red[(rl + 8) * RED_STRIDE + cl];
                a[0] = (a[0] + v0.x) * s2;
                a[1] = (a[1] + v0.y) * s2;
                a[2] = (a[2] + v1.x) * s2;
                a[3] = (a[3] + v1.y) * s2;
#pragma unroll
                for (int qq = 0; qq < 4; qq++)
                    fr = fmaf(w2 * a[qq], a[qq], fr);
                const int gr = i0 + rl;
                const int gc = j0 + cl;
                *(float2*)&C[(size_t)gr * DIM + gc]       = make_float2(a[0], a[1]);
                *(float2*)&C[(size_t)(gr + 8) * DIM + gc] = make_float2(a[2], a[3]);
                if (bi != bj) {
                    C[(size_t)gc * DIM + gr]           = a[0];
                    C[(size_t)(gc + 1) * DIM + gr]     = a[1];
                    C[(size_t)gc * DIM + gr + 8]       = a[2];
                    C[(size_t)(gc + 1) * DIM + gr + 8] = a[3];
                }
            }
        }
    }

    // ---- fused Frobenius + finalize ----
#pragma unroll
    for (int o = 16; o > 0; o >>= 1)
        fr += __shfl_xor_sync(0xffffffffu, fr, o);
    if (ksub == 0 && l == 0) sh_wsum[w] = fr;
    __syncthreads();
    if (tid == 0) {
        double tot = ((double)sh_wsum[0] + (double)sh_wsum[1]) +
                     ((double)sh_wsum[2] + (double)sh_wsum[3]);
        atomicAdd(&g_frob[z], tot);
        __threadfence();
        int tk = atomicAdd(&g_ctr[z], 1);
        if (tk == NTILE - 1) {
            g_ctr[z] = 0;
            __threadfence();
            double c = sqrt(g_frob[z]);
            g_inv[z] = (float)(1.0 / c);
            g_logacc[z] += log2(c) * wfin;
            g_frob[z] = 0.0;
        }
    }
}

// ============ Gram partial sum ============
__global__ void add_parts_kernel() {
    const int z = blockIdx.y;
    float4* d        = reinterpret_cast<float4*>(g_bufA[z]);
    const float4* p0 = reinterpret_cast<const float4*>(g_part[0][z]);
    const float4* p1 = reinterpret_cast<const float4*>(g_part[1][z]);
    const float4* p2 = reinterpret_cast<const float4*>(g_part[2][z]);
    const float4* p3 = reinterpret_cast<const float4*>(g_part[3][z]);
    const int n = DIM * DIM / 4;
    for (int i = blockIdx.x * blockDim.x + threadIdx.x; i < n;
         i += gridDim.x * blockDim.x) {
        float4 a = p0[i], b = p1[i], c = p2[i], e = p3[i];
        float4 o;
        o.x = (a.x + b.x) + (c.x + e.x);
        o.y = (a.y + b.y) + (c.y + e.y);
        o.z = (a.z + b.z) + (c.z + e.z);
        o.w = (a.w + b.w) + (c.w + e.w);
        d[i] = o;
    }
}

// ============ Power iteration on H_8 ============
__device__ __forceinline__ void grid_barrier(int n) {
    __syncthreads();
    if (threadIdx.x == 0) {
        __threadfence();
        int gen = *((volatile int*)&g_bgen);
        if (atomicAdd(&g_bcnt, 1) == n - 1) {
            g_bcnt = 0;
            __threadfence();
            atomicAdd(&g_bgen, 1);
        } else {
            while (*((volatile int*)&g_bgen) == gen) { }
        }
        __threadfence();
    }
    __syncthreads();
}

__global__ void __launch_bounds__(256, 1)
power_kernel(int src_sel)
{
    const int z  = blockIdx.y;
    const int bx = blockIdx.x;
    const float* Mz = (src_sel == 1) ? g_bufA[z] : g_bufB[z];
    const int tid  = threadIdx.x;
    const int lrow = tid >> 3, seg = tid & 7;
    const int grow = bx * 32 + lrow;

    __shared__ float xs[DIM];

    if (bx == 0) {
        for (int i = tid; i < DIM; i += 256) g_vec[z][0][i] = 1.0f;
    }
    grid_barrier(PWR_CTAS * 3);

    for (int it = 0; it < PWR_M; it++) {
        const int in = it & 1, out = in ^ 1;
        for (int i = tid; i < DIM; i += 256) xs[i] = g_vec[z][in][i];
        __syncthreads();

        const float4* hrow = (const float4*)(Mz + (size_t)grow * DIM + seg * 128);
        const float4* xv   = (const float4*)(xs + seg * 128);
        float s = 0.0f;
#pragma unroll 8
        for (int i2 = 0; i2 < 32; i2++) {
            float4 h = hrow[i2], x = xv[i2];
            s = fmaf(h.x, x.x, s); s = fmaf(h.y, x.y, s);
            s = fmaf(h.z, x.z, s); s = fmaf(h.w, x.w, s);
        }
        s += __shfl_xor_sync(0xffffffffu, s, 1);
        s += __shfl_xor_sync(0xffffffffu, s, 2);
        s += __shfl_xor_sync(0xffffffffu, s, 4);
        if (seg == 0) {
            g_vec[z][out][grow] = s;
            if (it == PWR_M - 1) {
                float px = xs[grow];
                atomicAdd(&g_pn[z][0], px * px);
                atomicAdd(&g_pn[z][1], s * s);
            }
        }
        grid_barrier(PWR_CTAS * 3);
    }

    if (bx == 0 && tid == 0) {
        double lam = (double)g_inv[z] *
                     sqrt((double)g_pn[z][1] / (double)g_pn[z][0]);
        g_logacc[z] += exp2(-(double)M_SQ) * log2(lam);
    }
}

__global__ void out_kernel(float* __restrict__ out) {
    double l0 = exp2(g_logacc[0]);
    double l1 = exp2(g_logacc[1]);
    double l2 = exp2(g_logacc[2]);
    out[0] = (float)(l0 + 0.5 * (l1 + l2));
}

extern "C" void kernel_launch(void* const* d_in, const int* in_sizes, int n_in,
                              void* d_out, int out_size)
{
    const float* f1 = (const float*)d_in[0];
    const float* f2 = (const float*)d_in[1];
    const float* f3 = (const float*)d_in[2];
    (void)in_sizes; (void)n_in; (void)out_size;

    static int configured = 0;
    if (!configured) {
        cudaFuncSetAttribute(ata_mma_kernel,
                             cudaFuncAttributeMaxDynamicSharedMemorySize, GSMEMB);
        cudaFuncSetAttribute(sq_mma_kernel,
                             cudaFuncAttributeMaxDynamicSharedMemorySize, SQ_SMEM);
        configured = 1;
    }

    init_kernel<<<1, 8>>>();

    // Gram: 4-way K-split into partials, then sum into bufA
    ata_mma_kernel<<<dim3(NTILE, KSPLIT, 3), 128, GSMEMB>>>(
        f1, f2, f3, NROWS / KSPLIT);
    add_parts_kernel<<<dim3(128, 3), 256>>>();

    int cur = 1;
    for (int k = 1; k <= M_SQ; k++) {
        int dst = 3 - cur;
        sq_mma_kernel<<<dim3(NTILE, 1, 3), 256, SQ_SMEM>>>(
            cur, dst, exp2(-(double)k));
        cur = dst;
    }

    // Power iteration on H_8 (lives in buf 'cur'); adds 2^-8 * log2(lam1).
    power_kernel<<<dim3(PWR_CTAS, 3), 256>>>(cur);

    out_kernel<<<1, 1>>>((float*)d_out);
}

// round 7
// speedup vs baseline: 1.1549x; 1.1549x over previous
#include <cuda_runtime.h>
#include <cuda_bf16.h>
#include <math.h>
#include <stdint.h>

// ---------------------------------------------------------------------------
// BSPLoss: out = lam1 + 0.5*(lam2+lam3), lam_i = top eigenvalue of F_i^T F_i.
// Gram (4-way K-split, proven) + 10 Frobenius-normalized symmetric squarings.
// Squarings: CTA tile 256x128 (8 warps of 64x64), K-split 2 into partials,
// merged by add+frob+finalize kernel.  All GEMMs mma.sync.m16n8k16 bf16
// hi/lo split (3 products, fp32 accum).
// ---------------------------------------------------------------------------

#define DIM    1024
#define NROWS  8192
#define M_SQ   10
#define NTILE  36
#define KSPLIT 4

// Gram kernel (KC=16, 128 threads) -- proven R5 config
#define KCG     16
#define GREGB   4096
#define GSTAGEB (4 * GREGB)
#define GSMEMB  (2 * GSTAGEB + 1024)

// Squaring kernel: tile 256x128, KC=16, double buffered
#define QTILES  20
#define KCQ     16
#define IREGB   8192                 // 16 rows * 512B
#define JREGB   4096                 // 16 rows * 256B
#define QSTAGEB (2 * IREGB + 2 * JREGB)   // 24 KB
#define QSMEM   (2 * QSTAGEB)             // 48 KB

__device__ __align__(16) float g_bufA[3][DIM * DIM];
__device__ __align__(16) float g_part[KSPLIT][3][DIM * DIM];
__device__ double g_frob[3];
__device__ float  g_inv[3];
__device__ double g_logacc[3];
__device__ int    g_ctr[3];

__global__ void init_kernel() {
    int i = threadIdx.x;
    if (i < 3) { g_frob[i] = 0.0; g_inv[i] = 1.0f; g_logacc[i] = 0.0; g_ctr[i] = 0; }
}

__device__ __forceinline__ uint32_t smem_u32(const void* p) {
    uint32_t a;
    asm("{ .reg .u64 t; cvta.to.shared.u64 t, %1; cvt.u32.u64 %0, t; }"
        : "=r"(a) : "l"(p));
    return a;
}

__device__ __forceinline__ void ldsm4t(uint32_t* r, uint32_t addr) {
    asm volatile("ldmatrix.sync.aligned.m8n8.x4.trans.shared.b16 {%0,%1,%2,%3}, [%4];"
                 : "=r"(r[0]), "=r"(r[1]), "=r"(r[2]), "=r"(r[3]) : "r"(addr));
}

__device__ __forceinline__ void mma16816(float* c, const uint32_t* a,
                                         uint32_t b0, uint32_t b1) {
    asm volatile("mma.sync.aligned.m16n8k16.row.col.f32.bf16.bf16.f32 "
                 "{%0,%1,%2,%3}, {%4,%5,%6,%7}, {%8,%9}, {%0,%1,%2,%3};"
                 : "+f"(c[0]), "+f"(c[1]), "+f"(c[2]), "+f"(c[3])
                 : "r"(a[0]), "r"(a[1]), "r"(a[2]), "r"(a[3]), "r"(b0), "r"(b1));
}

// 256B-row region swizzle (J / gram regions)
__device__ __forceinline__ uint32_t swz256(uint32_t base, int row, int chunk) {
    return base + row * 256 + ((chunk ^ (row & 7)) << 4);
}
// 512B-row region swizzle (I region of squaring kernel)
__device__ __forceinline__ uint32_t swz512(uint32_t base, int row, int chunk) {
    return base + row * 512 + (((chunk ^ (row & 7)) & 31) << 4) + ((chunk >> 5) << 9);
}

__device__ __forceinline__ void cvt_hl(float4 v, uint2& hi, uint2& lo) {
    __nv_bfloat162 h0 = __floats2bfloat162_rn(v.x, v.y);
    __nv_bfloat162 h1 = __floats2bfloat162_rn(v.z, v.w);
    __nv_bfloat162 l0 = __floats2bfloat162_rn(v.x - __bfloat162float(h0.x),
                                              v.y - __bfloat162float(h0.y));
    __nv_bfloat162 l1 = __floats2bfloat162_rn(v.z - __bfloat162float(h1.x),
                                              v.w - __bfloat162float(h1.y));
    hi.x = *(uint32_t*)&h0; hi.y = *(uint32_t*)&h1;
    lo.x = *(uint32_t*)&l0; lo.y = *(uint32_t*)&l1;
}

// ============ Gram kernel (proven R5): 128 thr, KC=16, K-split grid =========
__device__ __forceinline__ void gram_store_stage(char* bufp, const float4* rI,
                                                 const float4* rJ, int row, int c4) {
#pragma unroll
    for (int it = 0; it < 4; it++) {
        const int col4 = c4 + it * 8;
        const int chunk = col4 >> 1;
        const uint32_t off = (uint32_t)(row * 256) +
                             ((chunk ^ (row & 7)) << 4) + ((col4 & 1) * 8);
        uint2 hi, lo;
        cvt_hl(rI[it], hi, lo);
        *(uint2*)(bufp + off)         = hi;
        *(uint2*)(bufp + GREGB + off) = lo;
        cvt_hl(rJ[it], hi, lo);
        *(uint2*)(bufp + 2 * GREGB + off) = hi;
        *(uint2*)(bufp + 3 * GREGB + off) = lo;
    }
}

__device__ __forceinline__ void gram_compute(uint32_t u, float acc[4][8][4],
                                             int wm, int wn, int g, int tr) {
    const uint32_t IHI = u, ILO = u + GREGB, JHI = u + 2 * GREGB, JLO = u + 3 * GREGB;
    const int rowA = ((g & 2) ? 8 : 0) + tr;
    const int rowB = ((g & 1) ? 8 : 0) + tr;
    uint32_t ax[4][4], bh[4][4], bx[4][4];
#pragma unroll
    for (int mi = 0; mi < 4; mi++)
        ldsm4t(ax[mi], swz256(IHI, rowA, (wm >> 3) + mi * 2 + (g & 1)));
#pragma unroll
    for (int nb = 0; nb < 4; nb++)
        ldsm4t(bh[nb], swz256(JHI, rowB, (wn >> 3) + nb * 2 + (g >> 1)));
#pragma unroll
    for (int mi = 0; mi < 4; mi++)
#pragma unroll
        for (int nj = 0; nj < 8; nj++)
            mma16816(acc[mi][nj], ax[mi],
                     bh[nj >> 1][(nj & 1) * 2], bh[nj >> 1][(nj & 1) * 2 + 1]);
#pragma unroll
    for (int nb = 0; nb < 4; nb++)
        ldsm4t(bx[nb], swz256(JLO, rowB, (wn >> 3) + nb * 2 + (g >> 1)));
#pragma unroll
    for (int mi = 0; mi < 4; mi++)
#pragma unroll
        for (int nj = 0; nj < 8; nj++)
            mma16816(acc[mi][nj], ax[mi],
                     bx[nj >> 1][(nj & 1) * 2], bx[nj >> 1][(nj & 1) * 2 + 1]);
#pragma unroll
    for (int mi = 0; mi < 4; mi++)
        ldsm4t(ax[mi], swz256(ILO, rowA, (wm >> 3) + mi * 2 + (g & 1)));
#pragma unroll
    for (int mi = 0; mi < 4; mi++)
#pragma unroll
        for (int nj = 0; nj < 8; nj++)
            mma16816(acc[mi][nj], ax[mi],
                     bh[nj >> 1][(nj & 1) * 2], bh[nj >> 1][(nj & 1) * 2 + 1]);
}

__global__ void __launch_bounds__(128)
ata_mma_kernel(const float* __restrict__ a0, const float* __restrict__ a1,
               const float* __restrict__ a2, int Kper)
{
    extern __shared__ __align__(16) char dynsmem[];

    const int z = blockIdx.z;
    const float* A = (z == 0) ? a0 : ((z == 1) ? a1 : a2);
    float* C = g_part[blockIdx.y][z];

    int t = blockIdx.x, bi = 0;
    while (t >= 8 - bi) { t -= 8 - bi; bi++; }
    const int bj = bi + t;
    const int i0 = bi * 128, j0 = bj * 128;

    const int tid = threadIdx.x;
    const int w = tid >> 5, l = tid & 31;
    const int wm = (w >> 1) * 64, wn = (w & 1) * 64;
    const int tr = l & 7, g = l >> 3;
    const int row = tid >> 3, c4 = tid & 7;

    const uint32_t sb = smem_u32(dynsmem);
    const uint32_t ab = (sb + 1023u) & ~1023u;
    char* aptr = dynsmem + (ab - sb);

    float acc[4][8][4];
#pragma unroll
    for (int mi = 0; mi < 4; mi++)
#pragma unroll
        for (int nj = 0; nj < 8; nj++)
#pragma unroll
            for (int q = 0; q < 4; q++) acc[mi][nj][q] = 0.0f;

    const size_t kbase = (size_t)blockIdx.y * Kper;
    const float* pI = A + kbase * DIM + i0 + c4 * 4;
    const float* pJ = A + kbase * DIM + j0 + c4 * 4;

    const int S = Kper / KCG;
    float4 rI[4], rJ[4];
    {
        const size_t b0 = (size_t)row * DIM;
#pragma unroll
        for (int it = 0; it < 4; it++) {
            rI[it] = *(const float4*)(pI + b0 + it * 32);
            rJ[it] = *(const float4*)(pJ + b0 + it * 32);
        }
    }
    gram_store_stage(aptr, rI, rJ, row, c4);
    {
        const size_t b1 = (size_t)(KCG + row) * DIM;
#pragma unroll
        for (int it = 0; it < 4; it++) {
            rI[it] = *(const float4*)(pI + b1 + it * 32);
            rJ[it] = *(const float4*)(pJ + b1 + it * 32);
        }
    }
    __syncthreads();

    for (int s = 0; s < S; s++) {
        const int b = s & 1;
        if (s + 1 < S)
            gram_store_stage(aptr + (b ^ 1) * GSTAGEB, rI, rJ, row, c4);
        if (s + 2 < S) {
            const size_t bb = (size_t)((s + 2) * KCG + row) * DIM;
#pragma unroll
            for (int it = 0; it < 4; it++) {
                rI[it] = *(const float4*)(pI + bb + it * 32);
                rJ[it] = *(const float4*)(pJ + bb + it * 32);
            }
        }
        gram_compute(ab + b * GSTAGEB, acc, wm, wn, g, tr);
        __syncthreads();
    }

    const int r  = l >> 2;
    const int c2 = 2 * (l & 3);
#pragma unroll
    for (int mi = 0; mi < 4; mi++) {
#pragma unroll
        for (int nj = 0; nj < 8; nj++) {
            float* a = acc[mi][nj];
            const int gr = i0 + wm + mi * 16 + r;
            const int gc = j0 + wn + nj * 8 + c2;
            *(float2*)&C[(size_t)gr * DIM + gc]       = make_float2(a[0], a[1]);
            *(float2*)&C[(size_t)(gr + 8) * DIM + gc] = make_float2(a[2], a[3]);
            if (bi != bj) {
                C[(size_t)gc * DIM + gr]           = a[0];
                C[(size_t)(gc + 1) * DIM + gr]     = a[1];
                C[(size_t)gc * DIM + gr + 8]       = a[2];
                C[(size_t)(gc + 1) * DIM + gr + 8] = a[3];
            }
        }
    }
}

__global__ void add_parts_kernel() {
    const int z = blockIdx.y;
    float4* d        = reinterpret_cast<float4*>(g_bufA[z]);
    const float4* p0 = reinterpret_cast<const float4*>(g_part[0][z]);
    const float4* p1 = reinterpret_cast<const float4*>(g_part[1][z]);
    const float4* p2 = reinterpret_cast<const float4*>(g_part[2][z]);
    const float4* p3 = reinterpret_cast<const float4*>(g_part[3][z]);
    const int n = DIM * DIM / 4;
    for (int i = blockIdx.x * blockDim.x + threadIdx.x; i < n;
         i += gridDim.x * blockDim.x) {
        float4 a = p0[i], b = p1[i], c = p2[i], e = p3[i];
        float4 o;
        o.x = (a.x + b.x) + (c.x + e.x);
        o.y = (a.y + b.y) + (c.y + e.y);
        o.z = (a.z + b.z) + (c.z + e.z);
        o.w = (a.w + b.w) + (c.w + e.w);
        d[i] = o;
    }
}

// ============ Squaring kernel: 256 thr, tile 256x128, warps 64x64 ===========
__global__ void __launch_bounds__(256, 1)
sq2_mma_kernel()
{
    extern __shared__ __align__(16) char dynsmem[];

    const int z  = blockIdx.z;
    const int ky = blockIdx.y;          // k-half: 0 or 1
    const float* A = g_bufA[z];
    float* C = g_part[ky][z];

    // tile (bi: 256-row block 0..3, bj: 128-col block, bj >= 2*bi)
    int t = blockIdx.x, bi = 0;
    while (t >= 8 - 2 * bi) { t -= 8 - 2 * bi; bi++; }
    const int bj = 2 * bi + t;
    const int i0 = bi * 256, j0 = bj * 128;

    const int tid = threadIdx.x;
    const int w = tid >> 5, l = tid & 31;
    const int wm = (w >> 1) * 64, wn = (w & 1) * 64;
    const int tr = l & 7, g = l >> 3;
    const int trow = tid >> 4, tc = tid & 15;   // loader: 16 rows x 16 thr

    const float sv = g_inv[z];
    const float s2 = sv * sv;

    const uint32_t sb = smem_u32(dynsmem);
    char* aptr = dynsmem;

    float acc[4][8][4];
#pragma unroll
    for (int mi = 0; mi < 4; mi++)
#pragma unroll
        for (int nj = 0; nj < 8; nj++)
#pragma unroll
            for (int q = 0; q < 4; q++) acc[mi][nj][q] = 0.0f;

    const size_t kbase = (size_t)ky * (DIM / 2);
    const float* pI = A + kbase * DIM + i0 + tc * 4;
    const float* pJ = A + kbase * DIM + j0 + tc * 4;

    const int S = (DIM / 2) / KCQ;   // 32 stages of K=16
    float4 rI[4], rJ[2];

    // prologue
    {
        const size_t b0 = (size_t)trow * DIM;
#pragma unroll
        for (int it = 0; it < 4; it++) rI[it] = *(const float4*)(pI + b0 + it * 64);
#pragma unroll
        for (int it = 0; it < 2; it++) rJ[it] = *(const float4*)(pJ + b0 + it * 64);
    }
    // store stage 0
    {
        char* bufp = aptr;
#pragma unroll
        for (int it = 0; it < 4; it++) {
            const int col4 = tc + it * 16;
            const int chunk = col4 >> 1;
            const uint32_t off = (uint32_t)(trow * 512) +
                ((chunk ^ (trow & 7) ^ (chunk & 0x18 & 0)) << 4) + ((col4 & 1) * 8);
            // note: chunk in 0..31; XOR only low 3 bits
            const uint32_t offx = (uint32_t)(trow * 512) +
                (((chunk & 0x18) | ((chunk ^ (trow & 7)) & 7)) << 4) + ((col4 & 1) * 8);
            uint2 hi, lo;
            cvt_hl(rI[it], hi, lo);
            *(uint2*)(bufp + offx)         = hi;
            *(uint2*)(bufp + IREGB + offx) = lo;
            (void)off;
        }
#pragma unroll
        for (int it = 0; it < 2; it++) {
            const int col4 = tc + it * 16;
            const int chunk = col4 >> 1;
            const uint32_t off = (uint32_t)(trow * 256) +
                                 ((chunk ^ (trow & 7)) << 4) + ((col4 & 1) * 8);
            uint2 hi, lo;
            cvt_hl(rJ[it], hi, lo);
            *(uint2*)(bufp + 2 * IREGB + off)         = hi;
            *(uint2*)(bufp + 2 * IREGB + JREGB + off) = lo;
        }
    }
    // prefetch stage 1
    {
        const size_t b1 = (size_t)(KCQ + trow) * DIM;
#pragma unroll
        for (int it = 0; it < 4; it++) rI[it] = *(const float4*)(pI + b1 + it * 64);
#pragma unroll
        for (int it = 0; it < 2; it++) rJ[it] = *(const float4*)(pJ + b1 + it * 64);
    }
    __syncthreads();

    for (int s = 0; s < S; s++) {
        const int b = s & 1;
        if (s + 1 < S) {
            char* bufp = aptr + (b ^ 1) * QSTAGEB;
#pragma unroll
            for (int it = 0; it < 4; it++) {
                const int col4 = tc + it * 16;
                const int chunk = col4 >> 1;
                const uint32_t offx = (uint32_t)(trow * 512) +
                    (((chunk & 0x18) | ((chunk ^ (trow & 7)) & 7)) << 4) +
                    ((col4 & 1) * 8);
                uint2 hi, lo;
                cvt_hl(rI[it], hi, lo);
                *(uint2*)(bufp + offx)         = hi;
                *(uint2*)(bufp + IREGB + offx) = lo;
            }
#pragma unroll
            for (int it = 0; it < 2; it++) {
                const int col4 = tc + it * 16;
                const int chunk = col4 >> 1;
                const uint32_t off = (uint32_t)(trow * 256) +
                                     ((chunk ^ (trow & 7)) << 4) + ((col4 & 1) * 8);
                uint2 hi, lo;
                cvt_hl(rJ[it], hi, lo);
                *(uint2*)(bufp + 2 * IREGB + off)         = hi;
                *(uint2*)(bufp + 2 * IREGB + JREGB + off) = lo;
            }
        }
        if (s + 2 < S) {
            const size_t bb = (size_t)((s + 2) * KCQ + trow) * DIM;
#pragma unroll
            for (int it = 0; it < 4; it++) rI[it] = *(const float4*)(pI + bb + it * 64);
#pragma unroll
            for (int it = 0; it < 2; it++) rJ[it] = *(const float4*)(pJ + bb + it * 64);
        }
        // ---- compute one k16 step per warp ----
        {
            const uint32_t u = sb + b * QSTAGEB;
            const uint32_t IHI = u, ILO = u + IREGB;
            const uint32_t JHI = u + 2 * IREGB, JLO = u + 2 * IREGB + JREGB;
            const int rowA = ((g & 2) ? 8 : 0) + tr;
            const int rowB = ((g & 1) ? 8 : 0) + tr;
            uint32_t ax[4][4], bh[4][4], bx[4][4];
#pragma unroll
            for (int mi = 0; mi < 4; mi++) {
                const int ch = (wm >> 3) + mi * 2 + (g & 1);   // 0..31
                const uint32_t ad = IHI + rowA * 512 +
                    (((ch & 0x18) | ((ch ^ (rowA & 7)) & 7)) << 4);
                ldsm4t(ax[mi], ad);
            }
#pragma unroll
            for (int nb = 0; nb < 4; nb++)
                ldsm4t(bh[nb], swz256(JHI, rowB, (wn >> 3) + nb * 2 + (g >> 1)));
#pragma unroll
            for (int mi = 0; mi < 4; mi++)
#pragma unroll
                for (int nj = 0; nj < 8; nj++)
                    mma16816(acc[mi][nj], ax[mi],
                             bh[nj >> 1][(nj & 1) * 2], bh[nj >> 1][(nj & 1) * 2 + 1]);
#pragma unroll
            for (int nb = 0; nb < 4; nb++)
                ldsm4t(bx[nb], swz256(JLO, rowB, (wn >> 3) + nb * 2 + (g >> 1)));
#pragma unroll
            for (int mi = 0; mi < 4; mi++)
#pragma unroll
                for (int nj = 0; nj < 8; nj++)
                    mma16816(acc[mi][nj], ax[mi],
                             bx[nj >> 1][(nj & 1) * 2], bx[nj >> 1][(nj & 1) * 2 + 1]);
#pragma unroll
            for (int mi = 0; mi < 4; mi++) {
                const int ch = (wm >> 3) + mi * 2 + (g & 1);
                const uint32_t ad = ILO + rowA * 512 +
                    (((ch & 0x18) | ((ch ^ (rowA & 7)) & 7)) << 4);
                ldsm4t(ax[mi], ad);
            }
#pragma unroll
            for (int mi = 0; mi < 4; mi++)
#pragma unroll
                for (int nj = 0; nj < 8; nj++)
                    mma16816(acc[mi][nj], ax[mi],
                             bh[nj >> 1][(nj & 1) * 2], bh[nj >> 1][(nj & 1) * 2 + 1]);
        }
        __syncthreads();
    }

    // ---- epilogue: scale, store direct + mirror (strictly upper only) ----
    const int r  = l >> 2;
    const int c2 = 2 * (l & 3);
#pragma unroll
    for (int mi = 0; mi < 4; mi++) {
#pragma unroll
        for (int nj = 0; nj < 8; nj++) {
            float* a = acc[mi][nj];
#pragma unroll
            for (int q = 0; q < 4; q++) a[q] *= s2;
            const int gr = i0 + wm + mi * 16 + r;
            const int gc = j0 + wn + nj * 8 + c2;
            *(float2*)&C[(size_t)gr * DIM + gc]       = make_float2(a[0], a[1]);
            *(float2*)&C[(size_t)(gr + 8) * DIM + gc] = make_float2(a[2], a[3]);
            if (gc     > gr)     C[(size_t)gc * DIM + gr]           = a[0];
            if (gc + 1 > gr)     C[(size_t)(gc + 1) * DIM + gr]     = a[1];
            if (gc     > gr + 8) C[(size_t)gc * DIM + gr + 8]       = a[2];
            if (gc + 1 > gr + 8) C[(size_t)(gc + 1) * DIM + gr + 8] = a[3];
        }
    }
}

// ============ merge partials + Frobenius + finalize ============
__global__ void __launch_bounds__(256)
addfrob_kernel(int do_write, double wfin)
{
    const int z = blockIdx.y;
    const float4* p0 = reinterpret_cast<const float4*>(g_part[0][z]);
    const float4* p1 = reinterpret_cast<const float4*>(g_part[1][z]);
    float4* d = reinterpret_cast<float4*>(g_bufA[z]);
    const int n = DIM * DIM / 4;
    float fr = 0.0f;
    for (int i = blockIdx.x * blockDim.x + threadIdx.x; i < n;
         i += gridDim.x * blockDim.x) {
        float4 a = p0[i], b = p1[i];
        float4 v;
        v.x = a.x + b.x; v.y = a.y + b.y; v.z = a.z + b.z; v.w = a.w + b.w;
        if (do_write) d[i] = v;
        fr = fmaf(v.x, v.x, fr); fr = fmaf(v.y, v.y, fr);
        fr = fmaf(v.z, v.z, fr); fr = fmaf(v.w, v.w, fr);
    }
    __shared__ double sh[256];
    sh[threadIdx.x] = (double)fr;
    __syncthreads();
    for (int s = 128; s > 0; s >>= 1) {
        if (threadIdx.x < s) sh[threadIdx.x] += sh[threadIdx.x + s];
        __syncthreads();
    }
    if (threadIdx.x == 0) {
        atomicAdd(&g_frob[z], sh[0]);
        __threadfence();
        int tk = atomicAdd(&g_ctr[z], 1);
        if (tk == (int)gridDim.x - 1) {
            g_ctr[z] = 0;
            __threadfence();
            double c = sqrt(g_frob[z]);
            g_inv[z] = (float)(1.0 / c);
            g_logacc[z] += log2(c) * wfin;
            g_frob[z] = 0.0;
        }
    }
}

__global__ void out_kernel(float* __restrict__ out) {
    double l0 = exp2(g_logacc[0]);
    double l1 = exp2(g_logacc[1]);
    double l2 = exp2(g_logacc[2]);
    out[0] = (float)(l0 + 0.5 * (l1 + l2));
}

extern "C" void kernel_launch(void* const* d_in, const int* in_sizes, int n_in,
                              void* d_out, int out_size)
{
    const float* f1 = (const float*)d_in[0];
    const float* f2 = (const float*)d_in[1];
    const float* f3 = (const float*)d_in[2];
    (void)in_sizes; (void)n_in; (void)out_size;

    static int configured = 0;
    if (!configured) {
        cudaFuncSetAttribute(ata_mma_kernel,
                             cudaFuncAttributeMaxDynamicSharedMemorySize, GSMEMB);
        cudaFuncSetAttribute(sq2_mma_kernel,
                             cudaFuncAttributeMaxDynamicSharedMemorySize, QSMEM);
        configured = 1;
    }

    init_kernel<<<1, 4>>>();

    // Gram: 4-way K-split into partials, sum into bufA (unscaled, g_inv=1)
    ata_mma_kernel<<<dim3(NTILE, KSPLIT, 3), 128, GSMEMB>>>(
        f1, f2, f3, NROWS / KSPLIT);
    add_parts_kernel<<<dim3(128, 3), 256>>>();

    for (int k = 1; k <= M_SQ; k++) {
        sq2_mma_kernel<<<dim3(QTILES, 2, 3), 256, QSMEM>>>();
        addfrob_kernel<<<dim3(108, 3), 256>>>(k < M_SQ ? 1 : 0,
                                              exp2(-(double)k));
    }
    out_kernel<<<1, 1>>>((float*)d_out);
}